// round 17
// baseline (speedup 1.0000x reference)
#include <cuda_runtime.h>
#include <cstdint>
#include <math.h>

#define CNUM    128
#define SMAX    401
#define KST     8              // steps per barrier (FTZ-max for 4 pairs/lane)
#define HALO_L  2              // halo lanes (4 pairs each = 8 pair-hops = KST)
#define VALID_L 30
#define NW      2              // 2 warps * 30 lanes * 4 pairs = 240 pairs >= 202
#define NTH     (NW * 32)      // 64
#define NSLOT   (NW * VALID_L) // 60 slots (1 slot = 4 pairs = 8 states)
#define RING    64
#define MARGIN  20

// Scratch: softmax(y_pred) rows, [B][T][C] (64 MB).
__device__ float g_p[64 * 2000 * CNUM];

// ---------------------------------------------------------------------------
// Kernel 1: row softmax over C=128. One warp per (b,t) row. (unchanged)
// ---------------------------------------------------------------------------
__global__ void softmax_kernel(const float* __restrict__ y, int rows) {
    int gw   = (blockIdx.x * blockDim.x + threadIdx.x) >> 5;
    int lane = threadIdx.x & 31;
    if (gw >= rows) return;
    float4 v = reinterpret_cast<const float4*>(y)[(size_t)gw * 32 + lane];
    float m = fmaxf(fmaxf(v.x, v.y), fmaxf(v.z, v.w));
#pragma unroll
    for (int o = 16; o; o >>= 1) m = fmaxf(m, __shfl_xor_sync(0xffffffffu, m, o));
    float e0 = __expf(v.x - m), e1 = __expf(v.y - m);
    float e2 = __expf(v.z - m), e3 = __expf(v.w - m);
    float sm = e0 + e1 + e2 + e3;
#pragma unroll
    for (int o = 16; o; o >>= 1) sm += __shfl_xor_sync(0xffffffffu, sm, o);
    float inv = __frcp_rn(sm);
    reinterpret_cast<float4*>(g_p)[(size_t)gw * 32 + lane] =
        make_float4(e0 * inv, e1 * inv, e2 * inv, e3 * inv);
}

// ---------------------------------------------------------------------------
// Kernel 2: CTC alpha recursion, 4 pairs (8 states) per lane, 2 warps,
// 8 steps per barrier (R14 numerics, restructured boundary).
// Slot s = 30w + lane - 2 owns pairs 4s..4s+3 (warp1 lanes 0..1 = halo
// mirroring warp0 lanes 30..31; slot<0 lanes stay zero). Per-lane scale
// 2^ref fixed per block; 3-lane window (24 states) => FTZ-safe (86+20=106
// < 126 bits). Boundary restructure: per-lane exponent 'me' computed in
// the EPILOGUE (pre-barrier, off-chain); neighbor window max obtained via
// a 3rd PARALLEL shuffle (wmP = max(s1,s2,s3) == wm_{l-1}), with the warp
// seam corrected exactly from warp0's published me[27..31]. Removes the
// dependent ref-shuffle from the post-barrier critical chain. Bit-identical
// to R14 (seam lanes verified; warp0 low lanes have m1 == 0).
// ---------------------------------------------------------------------------
__device__ __forceinline__ void cp_async16(uint32_t saddr, const void* g) {
    asm volatile("cp.async.cg.shared.global [%0], [%1], 16;" :: "r"(saddr), "l"(g));
}
__device__ __forceinline__ float pw2c(int d) {   // exact 2^clamp(d,-127,127)
    return __int_as_float((min(max(d, -127), 127) + 127) << 23);
}

__global__ __launch_bounds__(NTH) void ctc_kernel(
    const int* __restrict__ labels, const int* __restrict__ in_len,
    const int* __restrict__ lab_len, float* __restrict__ out, int T, int L)
{
    __shared__ float s_y[RING][CNUM];     // 32 KB ring
    __shared__ int4  s_hA[2][HALO_L], s_hB[2][HALO_L];  // halo publish
    __shared__ int   s_hr[2][HALO_L];
    __shared__ int   s_me[2][5];          // warp0 lanes 27..31 exponents
    __shared__ int2  s_al[8 * NSLOT];     // final readout (480 states)

    const int b    = blockIdx.x;
    const int tid  = threadIdx.x;
    const int wid  = tid >> 5;
    const int lane = tid & 31;
    const float* pb = g_p + (size_t)b * T * CNUM;
    const int tend  = min(T, in_len[b]);

    const int slot = wid * VALID_L + lane - HALO_L;

    // Per-pair classes and skip flags (pairs q = 4*slot + qi)
    int   exc0, exc1, exc2, exc3;
    float sk0 = 0.f, sk1 = 0.f, sk2 = 0.f, sk3 = 0.f;
    {
        int e[4]; float s[4];
#pragma unroll
        for (int qi = 0; qi < 4; ++qi) {
            int q = 4 * slot + qi;
            int c = CNUM - 1; float sf = 0.f;
            if (slot >= 0 && q >= 0 && q < L) {
                int v = labels[b * L + q];
                c = (v < 0) ? 0 : v;
                if (q >= 1) {
                    int v2 = labels[b * L + q - 1];
                    v2 = (v2 < 0) ? 0 : v2;
                    sf = (c != v2) ? 1.f : 0.f;
                }
            }
            e[qi] = c; s[qi] = sf;
        }
        exc0 = e[0]; exc1 = e[1]; exc2 = e[2]; exc3 = e[3];
        sk0 = s[0]; sk1 = s[1]; sk2 = s[2]; sk3 = s[3];
    }

    uint32_t smy = (uint32_t)__cvta_generic_to_shared(&s_y[0][0]);

    // One 8-row group per call: warp w loads rows base+4w .. base+4w+3.
    auto issue_group = [&](int base) {
#pragma unroll
        for (int r = 0; r < 4; ++r) {
            int tn = base + 4 * wid + r;
            if (tn < T) cp_async16(smy + (uint32_t)(((tn & (RING - 1)) * CNUM + lane * 4) * 4),
                                   pb + (size_t)tn * CNUM + lane * 4);
        }
        asm volatile("cp.async.commit_group;");
    };

    // Prologue: rows 0..31 in 4 groups; wait 2 -> rows 0..15 complete.
    issue_group(0); issue_group(8); issue_group(16); issue_group(24);
    asm volatile("cp.async.wait_group 2;");
    __syncthreads();

    // t = 0 init (slot 0 = warp0 lane 2)
    float mE0 = 0.f, mL0 = 0.f, mE1 = 0.f, mL1 = 0.f;
    float mE2 = 0.f, mL2 = 0.f, mE3 = 0.f, mL3 = 0.f;
    int   ref = 0;
    if (slot == 0) { mE0 = s_y[0][CNUM - 1]; mL0 = s_y[0][exc0]; }

    // epilogue-style exponent + publish (parity 0)
    int me;
    {
        float fm = fmaxf(fmaxf(fmaxf(mE0, mL0), fmaxf(mE1, mL1)),
                         fmaxf(fmaxf(mE2, mL2), fmaxf(mE3, mL3)));
        me = ref + ((__float_as_int(fm) >> 23) - 127);
    }
    if (wid == 0 && lane >= 27) s_me[0][lane - 27] = me;
    if (wid == 0 && lane >= 32 - HALO_L) {
        int i = lane - (32 - HALO_L);
        s_hA[0][i] = make_int4(__float_as_int(mE0), __float_as_int(mL0),
                               __float_as_int(mE1), __float_as_int(mL1));
        s_hB[0][i] = make_int4(__float_as_int(mE2), __float_as_int(mL2),
                               __float_as_int(mE3), __float_as_int(mL3));
        s_hr[0][i] = ref;
    }
    __syncthreads();

    float fA = 1.f, fB = 1.f;
    auto boundary = [&](int par) {
        // halo adopt: values+ref+me come from warp0's publishes
        if (wid == 1 && lane < HALO_L) {
            int4 a = s_hA[par][lane], c = s_hB[par][lane];
            mE0 = __int_as_float(a.x); mL0 = __int_as_float(a.y);
            mE1 = __int_as_float(a.z); mL1 = __int_as_float(a.w);
            mE2 = __int_as_float(c.x); mL2 = __int_as_float(c.y);
            mE3 = __int_as_float(c.z); mL3 = __int_as_float(c.w);
            ref = s_hr[par][lane];
            me  = s_me[par][lane + 3];     // lane0 -> w0lane30, lane1 -> w0lane31
        }
        // 3 PARALLEL shuffles of epilogue-computed exponents
        int s1 = __shfl_up_sync(0xffffffffu, me, 1);
        int s2 = __shfl_up_sync(0xffffffffu, me, 2);
        int s3 = __shfl_up_sync(0xffffffffu, me, 3);
        // exact seam correction for warp1 lanes 0..2 (virtual lanes below)
        if (wid == 1) {
            if (lane == 0)      { s1 = s_me[par][2]; s2 = s_me[par][1]; s3 = s_me[par][0]; }
            else if (lane == 1) { s2 = s_me[par][2]; s3 = s_me[par][1]; }
            else if (lane == 2) { s3 = s_me[par][2]; }
        }
        int wm  = max(me, max(s1, s2));    // own window  (lanes l-2..l)
        int wmP = max(s1, max(s2, s3));    // == wm_{l-1} (lanes l-3..l-1)
        int refNew = wm + MARGIN;
        int dd = ref - refNew;
        int ddA = min(max(dd, -127), 127);
        float gA = pw2c(ddA), gB = pw2c(dd - ddA);
        mE0 = (mE0 * gA) * gB;  mL0 = (mL0 * gA) * gB;
        mE1 = (mE1 * gA) * gB;  mL1 = (mL1 * gA) * gB;
        mE2 = (mE2 * gA) * gB;  mL2 = (mL2 * gA) * gB;
        mE3 = (mE3 * gA) * gB;  mL3 = (mL3 * gA) * gB;
        ref = refNew;
        int d  = wmP - wm;                 // == r1New - refNew
        int dA = min(max(d, -127), 127);
        fA = pw2c(dA);  fB = pw2c(d - dA);
    };

    int par = 0;
    int t0 = 1;
    for (; t0 + KST <= tend; t0 += KST, par ^= 1) {
        boundary(par);
#pragma unroll
        for (int j = 0; j < KST; ++j) {
            const float* row = s_y[(t0 + j) & (RING - 1)];
            float pB = row[CNUM - 1];
            float p0 = row[exc0], p1 = row[exc1], p2 = row[exc2], p3 = row[exc3];
            float m1 = __shfl_up_sync(0xffffffffu, mL3, 1);
            float in0 = (m1 * fA) * fB;
            float nE0 = (mE0 + in0) * pB;
            float nL0 = fmaf(in0, sk0, mL0 + mE0) * p0;
            float nE1 = (mE1 + mL0) * pB;
            float nL1 = fmaf(mL0, sk1, mL1 + mE1) * p1;
            float nE2 = (mE2 + mL1) * pB;
            float nL2 = fmaf(mL1, sk2, mL2 + mE2) * p2;
            float nE3 = (mE3 + mL2) * pB;
            float nL3 = fmaf(mL2, sk3, mL3 + mE3) * p3;
            mE0 = nE0; mL0 = nL0; mE1 = nE1; mL1 = nL1;
            mE2 = nE2; mL2 = nL2; mE3 = nE3; mL3 = nL3;
        }
        // epilogue: exponent (off critical chain) + publishes for next block
        {
            float fm = fmaxf(fmaxf(fmaxf(mE0, mL0), fmaxf(mE1, mL1)),
                             fmaxf(fmaxf(mE2, mL2), fmaxf(mE3, mL3)));
            me = ref + ((__float_as_int(fm) >> 23) - 127);
        }
        if (wid == 0 && lane >= 27) s_me[par ^ 1][lane - 27] = me;
        if (wid == 0 && lane >= 32 - HALO_L) {
            int i = lane - (32 - HALO_L);
            s_hA[par ^ 1][i] = make_int4(__float_as_int(mE0), __float_as_int(mL0),
                                         __float_as_int(mE1), __float_as_int(mL1));
            s_hB[par ^ 1][i] = make_int4(__float_as_int(mE2), __float_as_int(mL2),
                                         __float_as_int(mE3), __float_as_int(mL3));
            s_hr[par ^ 1][i] = ref;
        }
        issue_group(t0 + 31);                  // rows t0+31 .. t0+38
        asm volatile("cp.async.wait_group 2;");
        __syncthreads();
    }

    // tail (< 8 steps; rows through t0+22 complete)
    if (t0 < tend) {
        boundary(par);
        for (int t = t0; t < tend; ++t) {
            const float* row = s_y[t & (RING - 1)];
            float pB = row[CNUM - 1];
            float p0 = row[exc0], p1 = row[exc1], p2 = row[exc2], p3 = row[exc3];
            float m1 = __shfl_up_sync(0xffffffffu, mL3, 1);
            float in0 = (m1 * fA) * fB;
            float nE0 = (mE0 + in0) * pB;
            float nL0 = fmaf(in0, sk0, mL0 + mE0) * p0;
            float nE1 = (mE1 + mL0) * pB;
            float nL1 = fmaf(mL0, sk1, mL1 + mE1) * p1;
            float nE2 = (mE2 + mL1) * pB;
            float nL2 = fmaf(mL1, sk2, mL2 + mE2) * p2;
            float nE3 = (mE3 + mL2) * pB;
            float nL3 = fmaf(mL2, sk3, mL3 + mE3) * p3;
            mE0 = nE0; mL0 = nL0; mE1 = nE1; mL1 = nL1;
            mE2 = nE2; mL2 = nL2; mE3 = nE3; mL3 = nL3;
        }
    }

    // final publish (valid lanes): states 8*slot .. 8*slot+7
    if (lane >= HALO_L) {
        s_al[8 * slot + 0] = make_int2(__float_as_int(mE0), ref);
        s_al[8 * slot + 1] = make_int2(__float_as_int(mL0), ref);
        s_al[8 * slot + 2] = make_int2(__float_as_int(mE1), ref);
        s_al[8 * slot + 3] = make_int2(__float_as_int(mL1), ref);
        s_al[8 * slot + 4] = make_int2(__float_as_int(mE2), ref);
        s_al[8 * slot + 5] = make_int2(__float_as_int(mL2), ref);
        s_al[8 * slot + 6] = make_int2(__float_as_int(mE3), ref);
        s_al[8 * slot + 7] = make_int2(__float_as_int(mL3), ref);
    }
    __syncthreads();

    if (tid == 0) {
        int se = 2 * lab_len[b];
        int sp = (se > 0) ? (se - 1) : 0;
        int2 A = s_al[se];
        int2 P = s_al[sp];
        double va = (double)__int_as_float(A.x);
        double vp = (double)__int_as_float(P.x);
        long long ra = (va > 0.0) ? (long long)A.y : (long long)(-(1ll << 40));
        long long rp = (vp > 0.0) ? (long long)P.y : (long long)(-(1ll << 40));
        long long rm = (ra > rp) ? ra : rp;
        double sum = 0.0;
        if (va > 0.0) sum += va * exp2((double)(ra - rm));
        if (vp > 0.0) sum += vp * exp2((double)(rp - rm));
        out[b] = (float)(-(log(sum) + (double)rm * 0.6931471805599453));
    }
}

// ---------------------------------------------------------------------------
extern "C" void kernel_launch(void* const* d_in, const int* in_sizes, int n_in,
                              void* d_out, int out_size) {
    const float* y  = (const float*)d_in[0];
    const int*   yt = (const int*)d_in[1];
    const int*   il = (const int*)d_in[2];
    const int*   ll = (const int*)d_in[3];
    int B = in_sizes[2];
    int L = in_sizes[1] / B;
    int rows = in_sizes[0] / CNUM;   // B*T
    int T = rows / B;

    int sm_blocks = (rows * 32 + 255) / 256;
    softmax_kernel<<<sm_blocks, 256>>>(y, rows);
    ctc_kernel<<<B, NTH>>>(yt, il, ll, (float*)d_out, T, L);
}